// round 5
// baseline (speedup 1.0000x reference)
#include <cuda_runtime.h>

// RegionPartitioner: extract 15x15 overlapping 64x64 regions (stride 32)
// from an edge-padded (8,4,500,500) fp32 tensor.
// out[b, r, c, i, j] = x[b, c, min(ri*32+i, 499), min(rj*32+j, 499)],
//   r = ri*15 + rj.  Output: (8, 225, 4, 64, 64) fp32.
//
// Grid: (C=4, B*R=1800). Block: 128 threads.
// Each thread: one float4 column x 8 consecutive region rows (128 B out).
// All 8 loads issued back-to-back (MLP=8), then 8 streaming stores (__stcs)
// so the write-once output doesn't evict the L2-resident input.

namespace {
constexpr int B  = 8;
constexpr int C  = 4;
constexpr int H  = 500;
constexpr int W  = 500;
constexpr int RS = 64;
constexpr int ST = 32;
constexpr int NR = 15;
constexpr int R  = NR * NR;   // 225
}  // namespace

__global__ __launch_bounds__(128)
void region_partition_kernel(const float* __restrict__ x,
                             float4* __restrict__ out) {
    const int rr = blockIdx.y;        // b*R + r   (0..1799)
    const int c  = blockIdx.x;        // 0..3
    const int r  = rr % R;
    const int b  = rr / R;
    const int ri = r / NR;
    const int rj = r % NR;

    const int t  = threadIdx.x;       // 0..127
    const int j4 = t & 15;            // float4 column within region row
    const int i0 = (t >> 4) << 3;     // starting region row: 0,8,...,56

    const int col0     = rj * ST + j4 * 4;
    const bool colfast = (col0 + 3 <= W - 1);

    const float* srcbase = x + (long long)(b * C + c) * H * W;

    // Gather 8 rows first -> MLP=8.
    float4 vals[8];
#pragma unroll
    for (int k = 0; k < 8; k++) {
        int row = ri * ST + i0 + k;
        if (row > H - 1) row = H - 1;                 // edge clamp (ri==14 only)
        const float* src = srcbase + row * W;
        if (colfast) {
            vals[k] = *reinterpret_cast<const float4*>(src + col0);
        } else {
            int c0 = min(col0,     W - 1);
            int c1 = min(col0 + 1, W - 1);
            int c2 = min(col0 + 2, W - 1);
            int c3 = min(col0 + 3, W - 1);
            vals[k].x = src[c0];
            vals[k].y = src[c1];
            vals[k].z = src[c2];
            vals[k].w = src[c3];
        }
    }

    // Streaming stores: within each k, 16 consecutive threads write 256B runs;
    // the whole block writes a contiguous 16KB tile.
    float4* dst = out + ((((long long)rr * C + c) * RS + i0) * (RS / 4) + j4);
#pragma unroll
    for (int k = 0; k < 8; k++) {
        __stcs(dst + k * (RS / 4), vals[k]);
    }
}

extern "C" void kernel_launch(void* const* d_in, const int* in_sizes, int n_in,
                              void* d_out, int out_size) {
    const float* x = (const float*)d_in[0];
    float4* out = (float4*)d_out;

    dim3 grid(C, B * R);   // (4, 1800)
    region_partition_kernel<<<grid, 128>>>(x, out);
}